// round 6
// baseline (speedup 1.0000x reference)
#include <cuda_runtime.h>
#include <cuda_bf16.h>
#include <math.h>

// ---------------- problem constants ----------------
#define BB     2
#define LL     1024
#define DD     1024
#define HH     16
#define FDIM   512
#define NLAYER 4
#define NVOC   5000
#define DFF    4096
#define SS     1026            // seqlen = 1 (graph) + 1 (sos) + L
#define MROWS  (BB*SS)         // 2052
#define OUTROWS (BB*(SS-1))    // 2050 output rows (skip graph row)

// ---------------- scratch (device globals; no allocation allowed) ----------------
__device__ float g_h  [BB*SS*DD];
__device__ float g_x  [BB*SS*DD];
__device__ float g_q  [BB*SS*DD];
__device__ float g_k  [BB*SS*DD];
__device__ float g_v  [BB*SS*DD];
__device__ float g_att[BB*SS*DD];
__device__ float g_t1 [BB*SS*DFF];
__device__ float g_t3 [BB*SS*DFF];

// ---------------- packed f32x2 helpers ----------------
__device__ __forceinline__ unsigned long long pack2(float x, float y) {
    unsigned long long r;
    asm("mov.b64 %0, {%1, %2};" : "=l"(r) : "f"(x), "f"(y));
    return r;
}
__device__ __forceinline__ void unpack2(unsigned long long v, float& x, float& y) {
    asm("mov.b64 {%0, %1}, %2;" : "=f"(x), "=f"(y) : "l"(v));
}
__device__ __forceinline__ void fma2(unsigned long long& c, unsigned long long a, unsigned long long b) {
    asm("fma.rn.f32x2 %0, %1, %2, %0;" : "+l"(c) : "l"(a), "l"(b));
}

union F4U { float4 f; unsigned long long u[2]; };

// ---------------- GEMM: C[M,N] (op) A[M,K] @ W[K,N] ----------------
// mode 0: C = A@W
// mode 1: C = A@W + E   (E = bias vector, length N)
// mode 2: C = C + A@W   (residual)
// mode 3: C = silu(E[m,n]) * (A@W)  (E = matrix, same layout as C)
// arm  1: A row index remap for logits: arow = (m/1025)*SS + 1 + m%1025
__global__ void __launch_bounds__(256, 2)
gemm_k(const float* __restrict__ A, const float* __restrict__ W,
       float* __restrict__ C, const float* __restrict__ E,
       int M, int N, int K, int mode, int arm)
{
    __shared__ float As[8][132];   // A^T tile: As[k][row], padded (conflict-free stores)
    __shared__ float Bs[8][128];   // B tile:   Bs[k][col]

    const int tid = threadIdx.x;
    const int bm = blockIdx.y * 128;
    const int bn = blockIdx.x * 128;

    // load indices
    const int lar = tid >> 1;            // 0..127 (row in A tile)
    const int lac = (tid & 1) << 2;      // 0 or 4 (k offset)
    const int lbr = tid >> 5;            // 0..7   (k row in B tile)
    const int lbc = (tid & 31) << 2;     // 0..124 (col in B tile)

    const int am = bm + lar;
    const bool avalid = (am < M);
    int arow = am;
    if (arm == 1 && avalid) arow = (am / 1025) * SS + 1 + (am % 1025);

    const float* ap = A + (size_t)arow * K + lac;
    const float* bp = W + (size_t)lbr * N + bn + lbc;
    const bool bvalid = (bn + lbc) < N;   // N is a multiple of 4, so float4 is all-in or all-out

    const int ty = tid >> 4, tx = tid & 15;
    const int rb = ty << 3, cb = tx << 3;

    unsigned long long cc[8][4];
    #pragma unroll
    for (int i = 0; i < 8; i++)
        #pragma unroll
        for (int j = 0; j < 4; j++) cc[i][j] = 0ull;

    const int nt = K >> 3;
    for (int kt = 0; kt < nt; kt++) {
        float4 a4 = avalid ? *(const float4*)ap : make_float4(0.f, 0.f, 0.f, 0.f);
        float4 b4 = bvalid ? *(const float4*)bp : make_float4(0.f, 0.f, 0.f, 0.f);
        __syncthreads();   // previous tile's compute done
        As[lac + 0][lar] = a4.x;
        As[lac + 1][lar] = a4.y;
        As[lac + 2][lar] = a4.z;
        As[lac + 3][lar] = a4.w;
        *(float4*)&Bs[lbr][lbc] = b4;
        __syncthreads();

        #pragma unroll
        for (int kk = 0; kk < 8; kk++) {
            F4U b0, b1;
            b0.f = *(const float4*)&Bs[kk][cb];
            b1.f = *(const float4*)&Bs[kk][cb + 4];
            float4 a0 = *(const float4*)&As[kk][rb];
            float4 a1 = *(const float4*)&As[kk][rb + 4];
            float av8[8] = {a0.x, a0.y, a0.z, a0.w, a1.x, a1.y, a1.z, a1.w};
            #pragma unroll
            for (int i = 0; i < 8; i++) {
                unsigned long long ad = pack2(av8[i], av8[i]);
                fma2(cc[i][0], ad, b0.u[0]);
                fma2(cc[i][1], ad, b0.u[1]);
                fma2(cc[i][2], ad, b1.u[0]);
                fma2(cc[i][3], ad, b1.u[1]);
            }
        }
        ap += 8;
        bp += (size_t)8 * N;
    }

    // epilogue
    #pragma unroll
    for (int i = 0; i < 8; i++) {
        const int m = bm + rb + i;
        if (m >= M) continue;
        float v[8];
        unpack2(cc[i][0], v[0], v[1]);
        unpack2(cc[i][1], v[2], v[3]);
        unpack2(cc[i][2], v[4], v[5]);
        unpack2(cc[i][3], v[6], v[7]);
        const size_t base = (size_t)m * N;
        #pragma unroll
        for (int j = 0; j < 8; j++) {
            const int c = bn + cb + j;
            if (c >= N) continue;
            float val = v[j];
            if (mode == 1)      val += E[c];
            else if (mode == 2) val += C[base + c];
            else if (mode == 3) { float t = E[base + c]; val *= t / (1.f + __expf(-t)); }
            C[base + c] = val;
        }
    }
}

// ---------------- embedding assembly ----------------
__device__ __forceinline__ float4 f4add(float4 a, float4 b) {
    a.x += b.x; a.y += b.y; a.z += b.z; a.w += b.w; return a;
}

__global__ void embed_k(const float* __restrict__ gf, const float* __restrict__ sos,
                        const float* __restrict__ nodee, const float* __restrict__ typee,
                        const float* __restrict__ pose, const int* __restrict__ sub)
{
    const int row = blockIdx.x;           // 0..MROWS-1
    const int b = row / SS, s = row % SS;
    const int t = threadIdx.x;            // float4 index, 256 * 4 = 1024 = D
    const int D4 = DD / 4;

    float4 acc = ((const float4*)pose)[(size_t)s * D4 + t];
    if (s == 0) {
        acc = f4add(acc, ((const float4*)gf)[(size_t)b * D4 + t]);
        acc = f4add(acc, ((const float4*)typee)[D4 + t]);        // type_emb[1]
    } else {
        float4 bv, ne;
        if (s == 1) {
            bv = ((const float4*)sos)[t];
            ne = ((const float4*)nodee)[t];                       // node_emb[0]
        } else {
            const int tok = b * LL + (s - 2);
            bv = ((const float4*)g_x)[(size_t)tok * D4 + t];      // proj result (+bias)
            ne = ((const float4*)nodee)[(size_t)sub[tok] * D4 + t];
        }
        acc = f4add(acc, bv);
        acc = f4add(acc, ne);
        acc = f4add(acc, ((const float4*)typee)[t]);              // type_emb[0]
    }
    ((float4*)g_h)[(size_t)row * D4 + t] = acc;
}

// ---------------- RMSNorm ----------------
__global__ void rmsnorm_k(const float* __restrict__ in, const float* __restrict__ w,
                          float* __restrict__ out)
{
    const int row = blockIdx.x;
    const int t = threadIdx.x;
    const int D4 = DD / 4;
    float4 v = ((const float4*)(in + (size_t)row * DD))[t];
    float ss = v.x * v.x + v.y * v.y + v.z * v.z + v.w * v.w;
    #pragma unroll
    for (int off = 16; off > 0; off >>= 1) ss += __shfl_xor_sync(0xffffffffu, ss, off);
    __shared__ float ws[8];
    if ((t & 31) == 0) ws[t >> 5] = ss;
    __syncthreads();
    float tot = ws[0] + ws[1] + ws[2] + ws[3] + ws[4] + ws[5] + ws[6] + ws[7];
    const float r = rsqrtf(tot * (1.0f / DD) + 1e-6f);
    float4 wv = ((const float4*)w)[t];
    float4 o;
    o.x = v.x * r * wv.x; o.y = v.y * r * wv.y;
    o.z = v.z * r * wv.z; o.w = v.w * r * wv.w;
    ((float4*)(out + (size_t)row * DD))[t] = o;
}

// ---------------- fused attention (flash-style) ----------------
// grid: (17 q-tiles, H, B); block: 256 threads; dynamic smem ~67 KB.
// Handles SPD graph bias on the fly and replicates the reference's fp32
// query-mask collapse (scores+(-1e9) flushes to exactly -1e9 -> uniform softmax).
#define ATT_P 65
#define ATT_SMEM_FLOATS (4 * 64 * ATT_P + 3 * 64)

__global__ void __launch_bounds__(256)
attn_k(const int* __restrict__ spd, const float* __restrict__ spde,
       const int* __restrict__ tmlp)
{
    extern __shared__ float smd[];
    float* Qs   = smd;                     // [64][P]  Q^T: Qs[d][i]
    float* Ks   = Qs + 64 * ATT_P;         // [64][P]  K^T: Ks[d][j]
    float* Vs   = Ks + 64 * ATT_P;         // [64][P]  V:   Vs[j][d]
    float* St   = Vs + 64 * ATT_P;         // [64][P]  P^T: St[j][i]
    float* rowm = St + 64 * ATT_P;
    float* rowl = rowm + 64;
    float* rowc = rowl + 64;
    __shared__ float sc[32];               // spd_emb column for this head

    const int tid = threadIdx.x;
    const int qt = blockIdx.x, h = blockIdx.y, b = blockIdx.z;
    const int q0 = qt * 64;
    int nq = SS - q0; if (nq > 64) nq = 64;
    const int limit = tmlp[b] + 2;

    if (tid < 32) sc[tid] = spde[tid * HH + h];
    if (tid < 64) { rowm[tid] = -1e30f; rowl[tid] = 0.f; rowc[tid] = 1.f; }

    const float* qb = g_q + ((size_t)(b * SS + q0)) * DD + h * 64;
    #pragma unroll
    for (int r = 0; r < 16; r++) {
        const int idx = tid + r * 256;
        const int qi = idx >> 6, d = idx & 63;
        Qs[d * ATT_P + qi] = (qi < nq) ? qb[(size_t)qi * DD + d] : 0.f;
    }

    const int ty = tid >> 4, tx = tid & 15;
    const int i0 = ty << 2, j0 = tx << 2;   // 4x4 micro-tile; j0 doubles as d0 for PV

    float oacc[4][4];
    #pragma unroll
    for (int a = 0; a < 4; a++)
        #pragma unroll
        for (int c = 0; c < 4; c++) oacc[a][c] = 0.f;

    for (int kt = 0; kt < (SS + 63) / 64; kt++) {
        const int k0 = kt * 64;
        int nk = SS - k0; if (nk > 64) nk = 64;
        __syncthreads();   // previous tile fully consumed

        const float* kb = g_k + ((size_t)(b * SS + k0)) * DD + h * 64;
        const float* vb = g_v + ((size_t)(b * SS + k0)) * DD + h * 64;
        #pragma unroll
        for (int r = 0; r < 16; r++) {
            const int idx = tid + r * 256;
            const int j = idx >> 6, d = idx & 63;
            const bool ok = (j < nk);
            Ks[d * ATT_P + j] = ok ? kb[(size_t)j * DD + d] : 0.f;
            Vs[j * ATT_P + d] = ok ? vb[(size_t)j * DD + d] : 0.f;
        }
        __syncthreads();

        // ---- scores: s[i][j] = sum_d Q[i][d] K[j][d] ----
        float sacc[4][4];
        #pragma unroll
        for (int a = 0; a < 4; a++)
            #pragma unroll
            for (int c = 0; c < 4; c++) sacc[a][c] = 0.f;

        #pragma unroll 4
        for (int d = 0; d < 64; d++) {
            float qv0 = Qs[d * ATT_P + i0 + 0];
            float qv1 = Qs[d * ATT_P + i0 + 1];
            float qv2 = Qs[d * ATT_P + i0 + 2];
            float qv3 = Qs[d * ATT_P + i0 + 3];
            float kv0 = Ks[d * ATT_P + j0 + 0];
            float kv1 = Ks[d * ATT_P + j0 + 1];
            float kv2 = Ks[d * ATT_P + j0 + 2];
            float kv3 = Ks[d * ATT_P + j0 + 3];
            sacc[0][0] += qv0 * kv0; sacc[0][1] += qv0 * kv1; sacc[0][2] += qv0 * kv2; sacc[0][3] += qv0 * kv3;
            sacc[1][0] += qv1 * kv0; sacc[1][1] += qv1 * kv1; sacc[1][2] += qv1 * kv2; sacc[1][3] += qv1 * kv3;
            sacc[2][0] += qv2 * kv0; sacc[2][1] += qv2 * kv1; sacc[2][2] += qv2 * kv2; sacc[2][3] += qv2 * kv3;
            sacc[3][0] += qv3 * kv0; sacc[3][1] += qv3 * kv1; sacc[3][2] += qv3 * kv2; sacc[3][3] += qv3 * kv3;
        }

        // ---- scale + bias + mask, write transposed tile ----
        #pragma unroll
        for (int ii = 0; ii < 4; ii++) {
            const int qi = i0 + ii;
            const int qg = q0 + qi;
            const bool qok = (qg < SS);
            const bool qmask = qok && (qg >= limit);
            #pragma unroll
            for (int jj = 0; jj < 4; jj++) {
                const int jl = j0 + jj;
                const int kg = k0 + jl;
                float o;
                if (!qok || jl >= nk) o = -1e30f;
                else if (qmask) o = 0.f;     // uniform softmax, exactly as ref's fp32 flush
                else {
                    int id;
                    if (qg >= 2 && kg >= 2)
                        id = spd[((size_t)b * LL + (qg - 2)) * LL + (kg - 2)];
                    else
                        id = (qg == kg) ? 0 : 31;
                    o = sacc[ii][jj] * 0.125f + sc[id];
                }
                St[jl * ATT_P + qi] = o;
            }
        }
        __syncthreads();

        // ---- online softmax, one thread per query row ----
        if (tid < nq) {
            const int i = tid;
            float mt = rowm[i];
            #pragma unroll 8
            for (int j = 0; j < 64; j++) mt = fmaxf(mt, St[j * ATT_P + i]);
            const float corr = __expf(rowm[i] - mt);
            float ls = 0.f;
            #pragma unroll 8
            for (int j = 0; j < 64; j++) {
                const float p = __expf(St[j * ATT_P + i] - mt);
                St[j * ATT_P + i] = p;
                ls += p;
            }
            rowl[i] = rowl[i] * corr + ls;
            rowm[i] = mt;
            rowc[i] = corr;
        }
        __syncthreads();

        // ---- PV accumulate ----
        float cr0 = rowc[i0 + 0], cr1 = rowc[i0 + 1], cr2 = rowc[i0 + 2], cr3 = rowc[i0 + 3];
        #pragma unroll
        for (int c = 0; c < 4; c++) {
            oacc[0][c] *= cr0; oacc[1][c] *= cr1; oacc[2][c] *= cr2; oacc[3][c] *= cr3;
        }
        #pragma unroll 4
        for (int j = 0; j < 64; j++) {
            float p0 = St[j * ATT_P + i0 + 0];
            float p1 = St[j * ATT_P + i0 + 1];
            float p2 = St[j * ATT_P + i0 + 2];
            float p3 = St[j * ATT_P + i0 + 3];
            float v0 = Vs[j * ATT_P + j0 + 0];
            float v1 = Vs[j * ATT_P + j0 + 1];
            float v2 = Vs[j * ATT_P + j0 + 2];
            float v3 = Vs[j * ATT_P + j0 + 3];
            oacc[0][0] += p0 * v0; oacc[0][1] += p0 * v1; oacc[0][2] += p0 * v2; oacc[0][3] += p0 * v3;
            oacc[1][0] += p1 * v0; oacc[1][1] += p1 * v1; oacc[1][2] += p1 * v2; oacc[1][3] += p1 * v3;
            oacc[2][0] += p2 * v0; oacc[2][1] += p2 * v1; oacc[2][2] += p2 * v2; oacc[2][3] += p2 * v3;
            oacc[3][0] += p3 * v0; oacc[3][1] += p3 * v1; oacc[3][2] += p3 * v2; oacc[3][3] += p3 * v3;
        }
    }

    // ---- write O ----
    #pragma unroll
    for (int ii = 0; ii < 4; ii++) {
        const int qi = i0 + ii;
        if (qi < nq) {
            const int qg = q0 + qi;
            const float inv = 1.f / rowl[qi];
            float* ob = g_att + ((size_t)(b * SS + qg)) * DD + h * 64 + j0;
            #pragma unroll
            for (int jj = 0; jj < 4; jj++) ob[jj] = oacc[ii][jj] * inv;
        }
    }
}

// ---------------- host driver ----------------
extern "C" void kernel_launch(void* const* d_in, const int* in_sizes, int n_in,
                              void* d_out, int out_size)
{
    const float* graph   = (const float*)d_in[0];
    const float* infeat  = (const float*)d_in[1];
    const float* projW   = (const float*)d_in[2];
    const float* projb   = (const float*)d_in[3];
    const float* sos     = (const float*)d_in[4];
    const float* nodee   = (const float*)d_in[5];
    const float* typee   = (const float*)d_in[6];
    const float* pose    = (const float*)d_in[7];
    const float* spde    = (const float*)d_in[8];
    const float* anorm   = (const float*)d_in[9];
    const float* wq      = (const float*)d_in[10];
    const float* wk      = (const float*)d_in[11];
    const float* wv      = (const float*)d_in[12];
    const float* wo      = (const float*)d_in[13];
    const float* fnorm   = (const float*)d_in[14];
    const float* w1      = (const float*)d_in[15];
    const float* w2      = (const float*)d_in[16];
    const float* w3      = (const float*)d_in[17];
    const float* finaln  = (const float*)d_in[18];
    const float* outW    = (const float*)d_in[19];
    const float* outb    = (const float*)d_in[20];
    const int*   sub     = (const int*)d_in[21];
    const int*   tml     = (const int*)d_in[22];
    const int*   spdidx  = (const int*)d_in[23];
    (void)d_in; (void)in_sizes; (void)n_in; (void)out_size;

    float *ph, *px, *pq, *pk, *pv, *patt, *pt1, *pt3;
    cudaGetSymbolAddress((void**)&ph,   g_h);
    cudaGetSymbolAddress((void**)&px,   g_x);
    cudaGetSymbolAddress((void**)&pq,   g_q);
    cudaGetSymbolAddress((void**)&pk,   g_k);
    cudaGetSymbolAddress((void**)&pv,   g_v);
    cudaGetSymbolAddress((void**)&patt, g_att);
    cudaGetSymbolAddress((void**)&pt1,  g_t1);
    cudaGetSymbolAddress((void**)&pt3,  g_t3);

    const int attSmem = ATT_SMEM_FLOATS * (int)sizeof(float);
    cudaFuncSetAttribute(attn_k, cudaFuncAttributeMaxDynamicSharedMemorySize, attSmem);

    auto gemm = [](const float* A, const float* W, float* C, const float* E,
                   int M, int N, int K, int mode, int arm) {
        dim3 g((N + 127) / 128, (M + 127) / 128);
        gemm_k<<<g, 256>>>(A, W, C, E, M, N, K, mode, arm);
    };

    // input projection (rows = B*L, bias fused), into g_x
    gemm(infeat, projW, px, projb, BB * LL, DD, FDIM, 1, 0);
    // assemble embeddings into g_h
    embed_k<<<MROWS, 256>>>(graph, sos, nodee, typee, pose, sub);

    for (int i = 0; i < NLAYER; i++) {
        const size_t wOff = (size_t)i * DD * DD;
        const size_t fOff = (size_t)i * DD * DFF;

        rmsnorm_k<<<MROWS, 256>>>(ph, anorm + (size_t)i * DD, px);
        gemm(px, wq + wOff, pq, nullptr, MROWS, DD, DD, 0, 0);
        gemm(px, wk + wOff, pk, nullptr, MROWS, DD, DD, 0, 0);
        gemm(px, wv + wOff, pv, nullptr, MROWS, DD, DD, 0, 0);

        attn_k<<<dim3((SS + 63) / 64, HH, BB), 256, attSmem>>>(spdidx, spde, tml);

        gemm(patt, wo + wOff, ph, nullptr, MROWS, DD, DD, 2, 0);   // h += att @ wo

        rmsnorm_k<<<MROWS, 256>>>(ph, fnorm + (size_t)i * DD, px);
        gemm(px, w1 + fOff, pt1, nullptr, MROWS, DFF, DD, 0, 0);   // t1 = x @ w1
        gemm(px, w3 + fOff, pt3, pt1,     MROWS, DFF, DD, 3, 0);   // g  = silu(t1) * (x @ w3)
        gemm(pt3, w2 + (size_t)i * DFF * DD, ph, nullptr, MROWS, DD, DFF, 2, 0); // h += g @ w2
    }

    rmsnorm_k<<<MROWS, 256>>>(ph, finaln, px);
    // logits: skip graph row of each batch via arow remap; bias fused
    gemm(px, outW, (float*)d_out, outb, OUTROWS, NVOC, DD, 1, 1);
}

// round 8
// speedup vs baseline: 3.7921x; 3.7921x over previous
#include <cuda_runtime.h>
#include <cuda_bf16.h>
#include <math.h>

// ---------------- problem constants ----------------
#define BB     2
#define LL     1024
#define DD     1024
#define HH     16
#define FDIM   512
#define NLAYER 4
#define NVOC   5000
#define DFF    4096
#define SS     1026            // seqlen = 1 (graph) + 1 (sos) + L
#define MROWS  (BB*SS)         // 2052
#define OUTROWS (BB*(SS-1))    // 2050 output rows (skip graph row)

// ---------------- scratch (device globals; no allocation allowed) ----------------
__device__ float g_h  [BB*SS*DD];
__device__ float g_x  [BB*SS*DD];
__device__ float g_q  [BB*SS*DD];
__device__ float g_k  [BB*SS*DD];
__device__ float g_v  [BB*SS*DD];
__device__ float g_att[BB*SS*DD];
__device__ float g_t1 [BB*SS*DFF];
__device__ float g_t3 [BB*SS*DFF];

// ---------------- tf32 helpers ----------------
__device__ __forceinline__ unsigned tf32cvt(float x) {
    unsigned r;
    asm("cvt.rna.tf32.f32 %0, %1;" : "=r"(r) : "f"(x));
    return r;
}
__device__ __forceinline__ void mma_tf32(float* d, const unsigned* a, const unsigned* b) {
    asm volatile(
        "mma.sync.aligned.m16n8k8.row.col.f32.tf32.tf32.f32 "
        "{%0,%1,%2,%3}, {%4,%5,%6,%7}, {%8,%9}, {%0,%1,%2,%3};"
        : "+f"(d[0]), "+f"(d[1]), "+f"(d[2]), "+f"(d[3])
        : "r"(a[0]), "r"(a[1]), "r"(a[2]), "r"(a[3]), "r"(b[0]), "r"(b[1]));
}

// ---------------- TF32 tensor-core GEMM ----------------
// C[M,N] (op) A[M,K] @ W[K,N], K % 16 == 0, N % 4 == 0.
// mode 0: C = A@W
// mode 1: C = A@W + E   (E = bias vector, length N)
// mode 2: C = C + A@W   (residual)
// mode 3: C = silu(E[m,n]) * (A@W)  (E = matrix, same layout as C)
// arm  1: A row remap for logits: arow = (m/1025)*SS + 1 + m%1025
#define AST 20    // As row stride (conflict-free: 20*lm+k hits all banks)
#define BST 136   // Bs row stride (conflict-free: 8*k+n distinct)

__global__ void __launch_bounds__(256)
gemm_tc(const float* __restrict__ A, const float* __restrict__ W,
        float* __restrict__ C, const float* __restrict__ E,
        int M, int N, int K, int mode, int arm)
{
    __shared__ unsigned As[2][128][AST];
    __shared__ unsigned Bs[2][16][BST];

    const int tid = threadIdx.x;
    const int bm = blockIdx.y * 128;
    const int bn = blockIdx.x * 128;

    // ---- gmem load indices (2 float4 per thread per matrix) ----
    // A: idx = tid + 256*r -> row = idx>>2 (0..127), col = (idx&3)*4
    const int a_r0 = tid >> 2;            // first row (0..63)
    const int a_c  = (tid & 3) << 2;      // k offset 0/4/8/12
    // B: idx = tid + 256*r -> krow = idx>>5 (0..15), col = (idx&31)*4
    const int b_k0 = tid >> 5;            // 0..7
    const int b_c  = (tid & 31) << 2;

    int am0 = bm + a_r0, am1 = bm + a_r0 + 64;
    const bool av0 = am0 < M, av1 = am1 < M;
    if (arm == 1) {
        if (av0) am0 = (am0 / 1025) * SS + 1 + (am0 % 1025);
        if (av1) am1 = (am1 / 1025) * SS + 1 + (am1 % 1025);
    }
    const float* ap0 = A + (size_t)am0 * K + a_c;
    const float* ap1 = A + (size_t)am1 * K + a_c;
    const float* bp0 = W + (size_t)b_k0 * N + bn + b_c;
    const float* bp1 = W + (size_t)(b_k0 + 8) * N + bn + b_c;
    const bool bv = (bn + b_c) < N;

    // ---- warp / fragment indices ----
    const int wid = tid >> 5, lane = tid & 31;
    const int wm = (wid >> 2) * 64;       // warp row base within tile
    const int wn = (wid & 3) * 32;        // warp col base within tile
    const int lm = lane >> 2;             // 0..7
    const int lk = lane & 3;              // 0..3

    float acc[4][4][4];
    #pragma unroll
    for (int i = 0; i < 4; i++)
        #pragma unroll
        for (int j = 0; j < 4; j++)
            #pragma unroll
            for (int r = 0; r < 4; r++) acc[i][j][r] = 0.f;

    const int nkt = K >> 4;
    float4 a4_0, a4_1, b4_0, b4_1;

    // preload tile 0
    a4_0 = av0 ? *(const float4*)ap0 : make_float4(0.f,0.f,0.f,0.f);
    a4_1 = av1 ? *(const float4*)ap1 : make_float4(0.f,0.f,0.f,0.f);
    b4_0 = bv  ? *(const float4*)bp0 : make_float4(0.f,0.f,0.f,0.f);
    b4_1 = bv  ? *(const float4*)bp1 : make_float4(0.f,0.f,0.f,0.f);

    int buf = 0;
    {   // store tile 0
        uint4 ua0 = { tf32cvt(a4_0.x), tf32cvt(a4_0.y), tf32cvt(a4_0.z), tf32cvt(a4_0.w) };
        uint4 ua1 = { tf32cvt(a4_1.x), tf32cvt(a4_1.y), tf32cvt(a4_1.z), tf32cvt(a4_1.w) };
        uint4 ub0 = { tf32cvt(b4_0.x), tf32cvt(b4_0.y), tf32cvt(b4_0.z), tf32cvt(b4_0.w) };
        uint4 ub1 = { tf32cvt(b4_1.x), tf32cvt(b4_1.y), tf32cvt(b4_1.z), tf32cvt(b4_1.w) };
        *(uint4*)&As[0][a_r0     ][a_c] = ua0;
        *(uint4*)&As[0][a_r0 + 64][a_c] = ua1;
        *(uint4*)&Bs[0][b_k0     ][b_c] = ub0;
        *(uint4*)&Bs[0][b_k0 + 8 ][b_c] = ub1;
    }
    __syncthreads();

    for (int kt = 0; kt < nkt; kt++) {
        // prefetch next tile into registers
        if (kt + 1 < nkt) {
            ap0 += 16; ap1 += 16;
            bp0 += (size_t)16 * N; bp1 += (size_t)16 * N;
            a4_0 = av0 ? *(const float4*)ap0 : make_float4(0.f,0.f,0.f,0.f);
            a4_1 = av1 ? *(const float4*)ap1 : make_float4(0.f,0.f,0.f,0.f);
            b4_0 = bv  ? *(const float4*)bp0 : make_float4(0.f,0.f,0.f,0.f);
            b4_1 = bv  ? *(const float4*)bp1 : make_float4(0.f,0.f,0.f,0.f);
        }

        // compute current buffer: 2 k-steps of 8
        #pragma unroll
        for (int ks = 0; ks < 2; ks++) {
            const int kb = ks * 8;
            unsigned af[4][4], bf[4][2];
            #pragma unroll
            for (int mt = 0; mt < 4; mt++) {
                const int r = wm + mt * 16 + lm;
                af[mt][0] = As[buf][r    ][kb + lk];
                af[mt][1] = As[buf][r + 8][kb + lk];
                af[mt][2] = As[buf][r    ][kb + lk + 4];
                af[mt][3] = As[buf][r + 8][kb + lk + 4];
            }
            #pragma unroll
            for (int nt = 0; nt < 4; nt++) {
                const int c = wn + nt * 8 + lm;
                bf[nt][0] = Bs[buf][kb + lk    ][c];
                bf[nt][1] = Bs[buf][kb + lk + 4][c];
            }
            #pragma unroll
            for (int mt = 0; mt < 4; mt++)
                #pragma unroll
                for (int nt = 0; nt < 4; nt++)
                    mma_tf32(acc[mt][nt], af[mt], bf[nt]);
        }

        // store prefetched tile into other buffer
        if (kt + 1 < nkt) {
            const int nb = buf ^ 1;
            uint4 ua0 = { tf32cvt(a4_0.x), tf32cvt(a4_0.y), tf32cvt(a4_0.z), tf32cvt(a4_0.w) };
            uint4 ua1 = { tf32cvt(a4_1.x), tf32cvt(a4_1.y), tf32cvt(a4_1.z), tf32cvt(a4_1.w) };
            uint4 ub0 = { tf32cvt(b4_0.x), tf32cvt(b4_0.y), tf32cvt(b4_0.z), tf32cvt(b4_0.w) };
            uint4 ub1 = { tf32cvt(b4_1.x), tf32cvt(b4_1.y), tf32cvt(b4_1.z), tf32cvt(b4_1.w) };
            *(uint4*)&As[nb][a_r0     ][a_c] = ua0;
            *(uint4*)&As[nb][a_r0 + 64][a_c] = ua1;
            *(uint4*)&Bs[nb][b_k0     ][b_c] = ub0;
            *(uint4*)&Bs[nb][b_k0 + 8 ][b_c] = ub1;
        }
        __syncthreads();
        buf ^= 1;
    }

    // ---- epilogue ----
    #pragma unroll
    for (int mt = 0; mt < 4; mt++) {
        #pragma unroll
        for (int rr = 0; rr < 2; rr++) {
            const int m = bm + wm + mt * 16 + lm + rr * 8;
            if (m >= M) continue;
            const size_t base = (size_t)m * N;
            #pragma unroll
            for (int nt = 0; nt < 4; nt++) {
                const int c = bn + wn + nt * 8 + 2 * lk;
                if (c >= N) continue;
                float v0 = acc[mt][nt][rr * 2 + 0];
                float v1 = acc[mt][nt][rr * 2 + 1];
                if (mode == 1)      { v0 += E[c]; v1 += E[c + 1]; }
                else if (mode == 2) { v0 += C[base + c]; v1 += C[base + c + 1]; }
                else if (mode == 3) {
                    float t0 = E[base + c], t1 = E[base + c + 1];
                    v0 *= t0 / (1.f + __expf(-t0));
                    v1 *= t1 / (1.f + __expf(-t1));
                }
                float2 o; o.x = v0; o.y = v1;
                *(float2*)&C[base + c] = o;
            }
        }
    }
}

// ---------------- embedding assembly ----------------
__device__ __forceinline__ float4 f4add(float4 a, float4 b) {
    a.x += b.x; a.y += b.y; a.z += b.z; a.w += b.w; return a;
}

__global__ void embed_k(const float* __restrict__ gf, const float* __restrict__ sos,
                        const float* __restrict__ nodee, const float* __restrict__ typee,
                        const float* __restrict__ pose, const int* __restrict__ sub)
{
    const int row = blockIdx.x;           // 0..MROWS-1
    const int b = row / SS, s = row % SS;
    const int t = threadIdx.x;            // float4 index, 256 * 4 = 1024 = D
    const int D4 = DD / 4;

    float4 acc = ((const float4*)pose)[(size_t)s * D4 + t];
    if (s == 0) {
        acc = f4add(acc, ((const float4*)gf)[(size_t)b * D4 + t]);
        acc = f4add(acc, ((const float4*)typee)[D4 + t]);        // type_emb[1]
    } else {
        float4 bv, ne;
        if (s == 1) {
            bv = ((const float4*)sos)[t];
            ne = ((const float4*)nodee)[t];                       // node_emb[0]
        } else {
            const int tok = b * LL + (s - 2);
            bv = ((const float4*)g_x)[(size_t)tok * D4 + t];      // proj result (+bias)
            ne = ((const float4*)nodee)[(size_t)sub[tok] * D4 + t];
        }
        acc = f4add(acc, bv);
        acc = f4add(acc, ne);
        acc = f4add(acc, ((const float4*)typee)[t]);              // type_emb[0]
    }
    ((float4*)g_h)[(size_t)row * D4 + t] = acc;
}

// ---------------- RMSNorm ----------------
__global__ void rmsnorm_k(const float* __restrict__ in, const float* __restrict__ w,
                          float* __restrict__ out)
{
    const int row = blockIdx.x;
    const int t = threadIdx.x;
    float4 v = ((const float4*)(in + (size_t)row * DD))[t];
    float ss = v.x * v.x + v.y * v.y + v.z * v.z + v.w * v.w;
    #pragma unroll
    for (int off = 16; off > 0; off >>= 1) ss += __shfl_xor_sync(0xffffffffu, ss, off);
    __shared__ float ws[8];
    if ((t & 31) == 0) ws[t >> 5] = ss;
    __syncthreads();
    float tot = ws[0] + ws[1] + ws[2] + ws[3] + ws[4] + ws[5] + ws[6] + ws[7];
    const float r = rsqrtf(tot * (1.0f / DD) + 1e-6f);
    float4 wv = ((const float4*)w)[t];
    float4 o;
    o.x = v.x * r * wv.x; o.y = v.y * r * wv.y;
    o.z = v.z * r * wv.z; o.w = v.w * r * wv.w;
    ((float4*)(out + (size_t)row * DD))[t] = o;
}

// ---------------- fused attention (flash-style, fp32) ----------------
#define ATT_P 65
#define ATT_SMEM_FLOATS (4 * 64 * ATT_P + 3 * 64)

__global__ void __launch_bounds__(256)
attn_k(const int* __restrict__ spd, const float* __restrict__ spde,
       const int* __restrict__ tmlp)
{
    extern __shared__ float smd[];
    float* Qs   = smd;                     // [64][P]  Q^T: Qs[d][i]
    float* Ks   = Qs + 64 * ATT_P;         // [64][P]  K^T: Ks[d][j]
    float* Vs   = Ks + 64 * ATT_P;         // [64][P]  V:   Vs[j][d]
    float* St   = Vs + 64 * ATT_P;         // [64][P]  P^T: St[j][i]
    float* rowm = St + 64 * ATT_P;
    float* rowl = rowm + 64;
    float* rowc = rowl + 64;
    __shared__ float sc[32];               // spd_emb column for this head

    const int tid = threadIdx.x;
    const int qt = blockIdx.x, h = blockIdx.y, b = blockIdx.z;
    const int q0 = qt * 64;
    int nq = SS - q0; if (nq > 64) nq = 64;
    const int limit = tmlp[b] + 2;

    if (tid < 32) sc[tid] = spde[tid * HH + h];
    if (tid < 64) { rowm[tid] = -1e30f; rowl[tid] = 0.f; rowc[tid] = 1.f; }

    const float* qb = g_q + ((size_t)(b * SS + q0)) * DD + h * 64;
    #pragma unroll
    for (int r = 0; r < 16; r++) {
        const int idx = tid + r * 256;
        const int qi = idx >> 6, d = idx & 63;
        Qs[d * ATT_P + qi] = (qi < nq) ? qb[(size_t)qi * DD + d] : 0.f;
    }

    const int ty = tid >> 4, tx = tid & 15;
    const int i0 = ty << 2, j0 = tx << 2;

    float oacc[4][4];
    #pragma unroll
    for (int a = 0; a < 4; a++)
        #pragma unroll
        for (int c = 0; c < 4; c++) oacc[a][c] = 0.f;

    for (int kt = 0; kt < (SS + 63) / 64; kt++) {
        const int k0 = kt * 64;
        int nk = SS - k0; if (nk > 64) nk = 64;
        __syncthreads();

        const float* kb = g_k + ((size_t)(b * SS + k0)) * DD + h * 64;
        const float* vb = g_v + ((size_t)(b * SS + k0)) * DD + h * 64;
        #pragma unroll
        for (int r = 0; r < 16; r++) {
            const int idx = tid + r * 256;
            const int j = idx >> 6, d = idx & 63;
            const bool ok = (j < nk);
            Ks[d * ATT_P + j] = ok ? kb[(size_t)j * DD + d] : 0.f;
            Vs[j * ATT_P + d] = ok ? vb[(size_t)j * DD + d] : 0.f;
        }
        __syncthreads();

        float sacc[4][4];
        #pragma unroll
        for (int a = 0; a < 4; a++)
            #pragma unroll
            for (int c = 0; c < 4; c++) sacc[a][c] = 0.f;

        #pragma unroll 4
        for (int d = 0; d < 64; d++) {
            float qv0 = Qs[d * ATT_P + i0 + 0];
            float qv1 = Qs[d * ATT_P + i0 + 1];
            float qv2 = Qs[d * ATT_P + i0 + 2];
            float qv3 = Qs[d * ATT_P + i0 + 3];
            float kv0 = Ks[d * ATT_P + j0 + 0];
            float kv1 = Ks[d * ATT_P + j0 + 1];
            float kv2 = Ks[d * ATT_P + j0 + 2];
            float kv3 = Ks[d * ATT_P + j0 + 3];
            sacc[0][0] += qv0 * kv0; sacc[0][1] += qv0 * kv1; sacc[0][2] += qv0 * kv2; sacc[0][3] += qv0 * kv3;
            sacc[1][0] += qv1 * kv0; sacc[1][1] += qv1 * kv1; sacc[1][2] += qv1 * kv2; sacc[1][3] += qv1 * kv3;
            sacc[2][0] += qv2 * kv0; sacc[2][1] += qv2 * kv1; sacc[2][2] += qv2 * kv2; sacc[2][3] += qv2 * kv3;
            sacc[3][0] += qv3 * kv0; sacc[3][1] += qv3 * kv1; sacc[3][2] += qv3 * kv2; sacc[3][3] += qv3 * kv3;
        }

        #pragma unroll
        for (int ii = 0; ii < 4; ii++) {
            const int qi = i0 + ii;
            const int qg = q0 + qi;
            const bool qok = (qg < SS);
            const bool qmask = qok && (qg >= limit);
            #pragma unroll
            for (int jj = 0; jj < 4; jj++) {
                const int jl = j0 + jj;
                const int kg = k0 + jl;
                float o;
                if (!qok || jl >= nk) o = -1e30f;
                else if (qmask) o = 0.f;     // ref's fp32 flush -> uniform softmax
                else {
                    int id;
                    if (qg >= 2 && kg >= 2)
                        id = spd[((size_t)b * LL + (qg - 2)) * LL + (kg - 2)];
                    else
                        id = (qg == kg) ? 0 : 31;
                    o = sacc[ii][jj] * 0.125f + sc[id];
                }
                St[jl * ATT_P + qi] = o;
            }
        }
        __syncthreads();

        if (tid < nq) {
            const int i = tid;
            float mt = rowm[i];
            #pragma unroll 8
            for (int j = 0; j < 64; j++) mt = fmaxf(mt, St[j * ATT_P + i]);
            const float corr = __expf(rowm[i] - mt);
            float ls = 0.f;
            #pragma unroll 8
            for (int j = 0; j < 64; j++) {
                const float p = __expf(St[j * ATT_P + i] - mt);
                St[j * ATT_P + i] = p;
                ls += p;
            }
            rowl[i] = rowl[i] * corr + ls;
            rowm[i] = mt;
            rowc[i] = corr;
        }
        __syncthreads();

        float cr0 = rowc[i0 + 0], cr1 = rowc[i0 + 1], cr2 = rowc[i0 + 2], cr3 = rowc[i0 + 3];
        #pragma unroll
        for (int c = 0; c < 4; c++) {
            oacc[0][c] *= cr0; oacc[1][c] *= cr1; oacc[2][c] *= cr2; oacc[3][c] *= cr3;
        }
        #pragma unroll 4
        for (int j = 0; j < 64; j++) {
            float p0 = St[j * ATT_P + i0 + 0];
            float p1 = St[j * ATT_P + i0 + 1];
            float p2 = St[j * ATT_P + i0 + 2];
            float p3 = St[j * ATT_P + i0 + 3];
            float v0 = Vs[j * ATT_P + j0 + 0];
            float v1 = Vs[j * ATT_P + j0 + 1];
            float v2 = Vs[j * ATT_P + j0 + 2];
            float v3 = Vs[j * ATT_P + j0 + 3];
            oacc[0][0] += p0 * v0; oacc[0][1] += p0 * v1; oacc[0][2] += p0 * v2; oacc[0][3] += p0 * v3;
            oacc[1][0] += p1 * v0; oacc[1][1] += p1 * v1; oacc[1][2] += p1 * v2; oacc[1][3] += p1 * v3;
            oacc[2][0] += p2 * v0; oacc[2][1] += p2 * v1; oacc[2][2] += p2 * v2; oacc[2][3] += p2 * v3;
            oacc[3][0] += p3 * v0; oacc[3][1] += p3 * v1; oacc[3][2] += p3 * v2; oacc[3][3] += p3 * v3;
        }
    }

    #pragma unroll
    for (int ii = 0; ii < 4; ii++) {
        const int qi = i0 + ii;
        if (qi < nq) {
            const int qg = q0 + qi;
            const float inv = 1.f / rowl[qi];
            float* ob = g_att + ((size_t)(b * SS + qg)) * DD + h * 64 + j0;
            #pragma unroll
            for (int jj = 0; jj < 4; jj++) ob[jj] = oacc[ii][jj] * inv;
        }
    }
}

// ---------------- host driver ----------------
extern "C" void kernel_launch(void* const* d_in, const int* in_sizes, int n_in,
                              void* d_out, int out_size)
{
    const float* graph   = (const float*)d_in[0];
    const float* infeat  = (const float*)d_in[1];
    const float* projW   = (const float*)d_in[2];
    const float* projb   = (const float*)d_in[3];
    const float* sos     = (const float*)d_in[4];
    const float* nodee   = (const float*)d_in[5];
    const float* typee   = (const float*)d_in[6];
    const float* pose    = (const float*)d_in[7];
    const float* spde    = (const float*)d_in[8];
    const float* anorm   = (const float*)d_in[9];
    const float* wq      = (const float*)d_in[10];
    const float* wk      = (const float*)d_in[11];
    const float* wv      = (const float*)d_in[12];
    const float* wo      = (const float*)d_in[13];
    const float* fnorm   = (const float*)d_in[14];
    const float* w1      = (const float*)d_in[15];
    const float* w2      = (const float*)d_in[16];
    const float* w3      = (const float*)d_in[17];
    const float* finaln  = (const float*)d_in[18];
    const float* outW    = (const float*)d_in[19];
    const float* outb    = (const float*)d_in[20];
    const int*   sub     = (const int*)d_in[21];
    const int*   tml     = (const int*)d_in[22];
    const int*   spdidx  = (const int*)d_in[23];
    (void)in_sizes; (void)n_in; (void)out_size;

    float *ph, *px, *pq, *pk, *pv, *patt, *pt1, *pt3;
    cudaGetSymbolAddress((void**)&ph,   g_h);
    cudaGetSymbolAddress((void**)&px,   g_x);
    cudaGetSymbolAddress((void**)&pq,   g_q);
    cudaGetSymbolAddress((void**)&pk,   g_k);
    cudaGetSymbolAddress((void**)&pv,   g_v);
    cudaGetSymbolAddress((void**)&patt, g_att);
    cudaGetSymbolAddress((void**)&pt1,  g_t1);
    cudaGetSymbolAddress((void**)&pt3,  g_t3);

    const int attSmem = ATT_SMEM_FLOATS * (int)sizeof(float);
    cudaFuncSetAttribute(attn_k, cudaFuncAttributeMaxDynamicSharedMemorySize, attSmem);

    auto gemm = [](const float* A, const float* W, float* C, const float* E,
                   int M, int N, int K, int mode, int arm) {
        dim3 g((N + 127) / 128, (M + 127) / 128);
        gemm_tc<<<g, 256>>>(A, W, C, E, M, N, K, mode, arm);
    };

    // input projection (rows = B*L, bias fused), into g_x
    gemm(infeat, projW, px, projb, BB * LL, DD, FDIM, 1, 0);
    // assemble embeddings into g_h
    embed_k<<<MROWS, 256>>>(graph, sos, nodee, typee, pose, sub);

    for (int i = 0; i < NLAYER; i++) {
        const size_t wOff = (size_t)i * DD * DD;
        const size_t fOff = (size_t)i * DD * DFF;

        rmsnorm_k<<<MROWS, 256>>>(ph, anorm + (size_t)i * DD, px);
        gemm(px, wq + wOff, pq, nullptr, MROWS, DD, DD, 0, 0);
        gemm(px, wk + wOff, pk, nullptr, MROWS, DD, DD, 0, 0);
        gemm(px, wv + wOff, pv, nullptr, MROWS, DD, DD, 0, 0);

        attn_k<<<dim3((SS + 63) / 64, HH, BB), 256, attSmem>>>(spdidx, spde, tml);

        gemm(patt, wo + wOff, ph, nullptr, MROWS, DD, DD, 2, 0);   // h += att @ wo

        rmsnorm_k<<<MROWS, 256>>>(ph, fnorm + (size_t)i * DD, px);
        gemm(px, w1 + fOff, pt1, nullptr, MROWS, DFF, DD, 0, 0);   // t1 = x @ w1
        gemm(px, w3 + fOff, pt3, pt1,     MROWS, DFF, DD, 3, 0);   // g  = silu(t1) * (x @ w3)
        gemm(pt3, w2 + (size_t)i * DFF * DD, ph, nullptr, MROWS, DD, DFF, 2, 0); // h += g @ w2
    }

    rmsnorm_k<<<MROWS, 256>>>(ph, finaln, px);
    // logits: skip graph row of each batch via arow remap; bias fused
    gemm(px, outW, (float*)d_out, outb, OUTROWS, NVOC, DD, 1, 1);
}